// round 9
// baseline (speedup 1.0000x reference)
#include <cuda_runtime.h>

// Problem constants: imgs (64, 3, 512, 512) f32, xform_params (64, 2) f32.
constexpr int BATCH = 64;
constexpr int HW    = 512 * 512;      // 262144 pixels per channel plane
constexpr int VEC   = HW / 4;         // 65536 float4 vectors per plane
constexpr int THREADS = 256;
constexpr int PER    = 4;             // float4 vectors per thread per channel
constexpr int BLOCK_VECS = THREADS * PER;   // 1024 vectors per block (fits in one plane)

__device__ __forceinline__ float clip01(float x) {
    return fminf(fmaxf(x, 0.0f), 1.0f);
}

// One hue-to-rgb channel: v - vs*clamp(min(k, 4-k), 0, 1), k = (h6 + n) mod 6.
// h6 in [0,6], n in {5,3,1} -> h6+n in [1,11]; one conditional -6 suffices.
__device__ __forceinline__ float hue_chan(float h6, float n, float v, float vs) {
    float k = h6 + n;
    k = (k >= 6.0f) ? k - 6.0f : k;
    float m = clip01(fminf(k, 4.0f - k));
    return fmaf(-vs, m, v);   // v * (1 - s*m)
}

__device__ __forceinline__ void adjust_pixel(float r, float g, float b,
                                             float dh6, float ds,
                                             float& ro, float& go, float& bo) {
    // ---- rgb2hsv (hue in sextant units) ----
    float maxc = fmaxf(r, fmaxf(g, b));
    float minc = fminf(r, fminf(g, b));
    float cr   = maxc - minc;
    float crd  = (cr == 0.0f) ? 1.0f : cr;
    float inv  = __fdividef(1.0f, crd);    // MUFU.RCP path, <=2 ulp

    bool is_r = (maxc == r);
    bool is_g = (maxc == g);

    // bc-gc = (g-b)*inv ; 2+rc-bc = 2+(b-r)*inv ; 4+gc-rc = 4+(r-g)*inv
    float hsum = is_r ? (g - b) * inv
               : (is_g ? fmaf(b - r, inv, 2.0f)
                       : fmaf(r - g, inv, 4.0f));      // in [-1, 5]

    // ---- fused hue shift + mod 6 ----
    float h6 = hsum + dh6;                 // in [-4, 8)
    h6 = (h6 < 0.0f)  ? h6 + 6.0f : h6;
    h6 = (h6 >= 6.0f) ? h6 - 6.0f : h6;    // in [0, 6]

    // ---- saturation adjust, algebraically fused ----
    // vs = v * clip01((cr/maxc)*ds) == min(cr*ds, maxc)   (s >= 0 always)
    float v  = maxc;
    float vs = fminf(cr * ds, maxc);

    // ---- hsv2rgb, branchless ----
    ro = hue_chan(h6, 5.0f, v, vs);
    go = hue_chan(h6, 3.0f, v, vs);
    bo = hue_chan(h6, 1.0f, v, vs);
}

__device__ __forceinline__ void process_vec(const float4& r4, const float4& g4, const float4& b4,
                                            float dh6, float ds,
                                            float4& r_out, float4& g_out, float4& b_out) {
    float ri[4] = {r4.x, r4.y, r4.z, r4.w};
    float gi[4] = {g4.x, g4.y, g4.z, g4.w};
    float bi[4] = {b4.x, b4.y, b4.z, b4.w};
    float ro[4], go[4], bo[4];
    #pragma unroll
    for (int k = 0; k < 4; k++)
        adjust_pixel(ri[k], gi[k], bi[k], dh6, ds, ro[k], go[k], bo[k]);
    r_out = make_float4(ro[0], ro[1], ro[2], ro[3]);
    g_out = make_float4(go[0], go[1], go[2], go[3]);
    b_out = make_float4(bo[0], bo[1], bo[2], bo[3]);
}

__global__ void __launch_bounds__(THREADS, 4)
adjust_hue_sat_kernel(const float* __restrict__ img,
                      const float* __restrict__ xp,
                      float* __restrict__ out) {
    // Each block covers BLOCK_VECS=1024 consecutive float4 vectors (within one batch).
    int vi0 = blockIdx.x * BLOCK_VECS + threadIdx.x;
    int b   = vi0 >> 16;                            // vi0 / VEC (VEC = 65536)
    int off0 = (vi0 & (VEC - 1)) << 2;              // pixel offset within plane

    float dh6 = __ldg(&xp[2 * b + 0]) * 6.0f;
    float ds  = __ldg(&xp[2 * b + 1]);

    size_t base = (size_t)b * 3 * HW + off0;

    // Front-batch all 12 loads (deep MLP keeps the DRAM request queue full).
    float4 r[PER], g[PER], bl[PER];
    #pragma unroll
    for (int j = 0; j < PER; j++) {
        size_t bj = base + (size_t)j * THREADS * 4;
        r[j]  = __ldcs(reinterpret_cast<const float4*>(img + bj));
        g[j]  = __ldcs(reinterpret_cast<const float4*>(img + bj + HW));
        bl[j] = __ldcs(reinterpret_cast<const float4*>(img + bj + 2 * HW));
    }

    // Compute + store per vector; stores interleave with remaining compute,
    // smoothing the write stream into the read stream.
    #pragma unroll
    for (int j = 0; j < PER; j++) {
        size_t bj = base + (size_t)j * THREADS * 4;
        float4 ro, go, bo;
        process_vec(r[j], g[j], bl[j], dh6, ds, ro, go, bo);
        __stcs(reinterpret_cast<float4*>(out + bj),          ro);
        __stcs(reinterpret_cast<float4*>(out + bj + HW),     go);
        __stcs(reinterpret_cast<float4*>(out + bj + 2 * HW), bo);
    }
}

extern "C" void kernel_launch(void* const* d_in, const int* in_sizes, int n_in,
                              void* d_out, int out_size) {
    const float* img = (const float*)d_in[0];
    const float* xp  = (const float*)d_in[1];
    float* out = (float*)d_out;

    int total_vec = BATCH * VEC;                     // 4,194,304 float4 vectors
    int blocks = total_vec / BLOCK_VECS;             // 4,096 blocks
    adjust_hue_sat_kernel<<<blocks, THREADS>>>(img, xp, out);
}